// round 12
// baseline (speedup 1.0000x reference)
#include <cuda_runtime.h>
#include <cuda_bf16.h>
#include <cuda_fp16.h>
#include <cstdint>
#include <math.h>

#define BB 4
#define LL 8192
#define DD 256
#define NLEV 13
#define NOUT 512

// ---------------- scratch (static device globals; no allocation) ----------------
__device__ float g_xt[BB * DD * LL];          // rmsnorm'd x, (b,d,t) layout
__device__ __half g_yth[BB * DD * LL];        // gelu output fp16, (b,d,t) = (k,m) layout
__device__ uint32_t g_whp[NOUT * (DD / 2)];   // W^T reordered into GLU pairs, fp16 k-pair packed
__device__ float g_br[NOUT];                  // reordered bias

// ---------------- kernel 0: weight prep (fp16 + transpose + pair-reorder) -------
__global__ void prep_kernel(const float* __restrict__ cw, const float* __restrict__ cb) {
    int idx = blockIdx.x * 256 + threadIdx.x;
    int n = idx >> 7;
    int kp = idx & 127;
    int k0 = kp * 2;
    int oc = (n & 1) ? (DD + (n >> 1)) : (n >> 1);
    float v0 = cw[k0 * NOUT + oc];
    float v1 = cw[(k0 + 1) * NOUT + oc];
    __half2 h = __floats2half2_rn(v0, v1);
    g_whp[n * 128 + kp] = *(uint32_t*)&h;
    if (idx < NOUT) {
        int occ = (idx & 1) ? (DD + (idx >> 1)) : (idx >> 1);
        g_br[idx] = cb[occ];
    }
}

// ---------------- kernel 1: rmsnorm + transpose to (b,d,t) ----------------------
__global__ void rmsnorm_kernel(const float* __restrict__ x, const float* __restrict__ rs) {
    __shared__ float tile[32][257];
    int b = blockIdx.x >> 8;
    int t0 = (blockIdx.x & 255) * 32;
    int w = threadIdx.x >> 5, lane = threadIdx.x & 31;
    #pragma unroll
    for (int rr = 0; rr < 4; rr++) {
        int tr = w * 4 + rr;
        size_t base = ((size_t)(b * LL + t0 + tr)) * DD;
        float v[8]; float ss = 0.f;
        #pragma unroll
        for (int k = 0; k < 8; k++) { v[k] = x[base + lane + 32 * k]; ss += v[k] * v[k]; }
        #pragma unroll
        for (int o = 16; o > 0; o >>= 1) ss += __shfl_xor_sync(0xffffffffu, ss, o);
        float inv = rsqrtf(ss * (1.f / DD) + 1e-6f);
        #pragma unroll
        for (int k = 0; k < 8; k++) tile[tr][lane + 32 * k] = v[k] * inv * rs[lane + 32 * k];
    }
    __syncthreads();
    #pragma unroll 8
    for (int dd = 0; dd < 32; dd++) {
        int d = w * 32 + dd;
        g_xt[((size_t)(b * DD + d)) * LL + t0 + lane] = tile[lane][d];
    }
}

// ---------------- kernel 2: 13-level dilated depthwise cascade + gelu -----------
__device__ __forceinline__ float gelu_f(float v) {
    float u = 0.7978845608028654f * (v + 0.044715f * v * v * v);
    return 0.5f * v * (1.f + tanhf(u));
}

__global__ void __launch_bounds__(256)
cascade_kernel(const float* __restrict__ h0,
               const float* __restrict__ h1,
               const float* __restrict__ wv) {
    extern __shared__ float sb[];
    float* srcb = sb;
    float* dstb = sb + LL;
    int b = blockIdx.x >> 8, d = blockIdx.x & 255;
    float h00 = h0[d * 2], h01 = h0[d * 2 + 1];
    float h10 = h1[d * 2], h11 = h1[d * 2 + 1];
    float w0 = wv[d];
    float wlast = wv[(NLEV + 1) * DD + d];
    size_t base = ((size_t)(b * DD + d)) * LL;
    int tid = threadIdx.x;
    float a[32], y[32];
    #pragma unroll
    for (int k = 0; k < 32; k++) {
        int t = tid + 256 * k;
        a[k] = g_xt[base + t];
        srcb[t] = a[k];
        y[k] = w0 * a[k];
    }
    for (int j = 0; j < 8; j++) {
        int dil = 1 << j;
        float wj = wv[(j + 1) * DD + d];
        __syncthreads();
        #pragma unroll
        for (int k = 0; k < 32; k++) {
            int t = tid + 256 * k;
            float prev = (t >= dil) ? srcb[t - dil] : 0.f;
            y[k] += wj * (h10 * prev + h11 * a[k]);
            a[k] = h00 * prev + h01 * a[k];
            if (j != 7) dstb[t] = a[k];
        }
        float* tmp = srcb; srcb = dstb; dstb = tmp;
    }
    #pragma unroll
    for (int j = 8; j < NLEV; j++) {
        int c = 1 << (j - 8);
        float wj = wv[(j + 1) * DD + d];
        #pragma unroll
        for (int k = 31; k >= 0; k--) {
            float prev = (k >= c) ? a[k - c] : 0.f;
            y[k] += wj * (h10 * prev + h11 * a[k]);
            a[k] = h00 * prev + h01 * a[k];
        }
    }
    #pragma unroll
    for (int k = 0; k < 32; k++) {
        int t = tid + 256 * k;
        g_yth[base + t] = __float2half_rn(gelu_f(y[k] + wlast * a[k]));
    }
}

// ---------------- kernel 3: cp.async + ldmatrix.trans GEMM + GLU + residual -----
// A^T lives in g_yth as (k=d, m=t): rows of 256B are contiguous -> coalesced
// cp.async into [k][m] smem (pitch 272B); ldmatrix.x4.trans turns stored 8x8
// (k,m) tiles into mma A fragments directly. No separate transpose pass.
__device__ __forceinline__ void mma16816(float* c, const uint32_t* a, const uint32_t* b) {
    asm("mma.sync.aligned.m16n8k16.row.col.f32.f16.f16.f32 "
        "{%0,%1,%2,%3}, {%4,%5,%6,%7}, {%8,%9}, {%0,%1,%2,%3};\n"
        : "+f"(c[0]), "+f"(c[1]), "+f"(c[2]), "+f"(c[3])
        : "r"(a[0]), "r"(a[1]), "r"(a[2]), "r"(a[3]), "r"(b[0]), "r"(b[1]));
}
__device__ __forceinline__ void ldsm4(uint32_t* r, uint32_t addr) {
    asm volatile("ldmatrix.sync.aligned.m8n8.x4.shared.b16 {%0,%1,%2,%3}, [%4];"
                 : "=r"(r[0]), "=r"(r[1]), "=r"(r[2]), "=r"(r[3]) : "r"(addr));
}
__device__ __forceinline__ void ldsm4t(uint32_t* r, uint32_t addr) {
    asm volatile("ldmatrix.sync.aligned.m8n8.x4.trans.shared.b16 {%0,%1,%2,%3}, [%4];"
                 : "=r"(r[0]), "=r"(r[1]), "=r"(r[2]), "=r"(r[3]) : "r"(addr));
}
__device__ __forceinline__ uint32_t smem_u32(const void* p) {
    uint32_t a;
    asm("{ .reg .u64 t; cvta.to.shared.u64 t, %1; cvt.u32.u64 %0, t; }" : "=r"(a) : "l"(p));
    return a;
}
__device__ __forceinline__ void cpasync16(uint32_t dst, const void* src) {
    asm volatile("cp.async.cg.shared.global [%0], [%1], 16;" :: "r"(dst), "l"(src));
}

// smem layout (bytes):
//   B:      [n=128][pitch 132 words]            = 67584
//   A bufs: 2 x [k=64][m=128 fp16, pitch 272B]  = 2*17408 = 34816
#define B_BYTES   67584
#define APITCH    272
#define ACHUNK    (64 * APITCH)
#define GEMM_SMEM (B_BYTES + 2 * ACHUNK)

__global__ void __launch_bounds__(512, 2)
gemm_glu_mma_kernel(const float* __restrict__ xin, float* __restrict__ out) {
    extern __shared__ char smem[];
    uint32_t sbase = smem_u32(smem);
    uint32_t b_smem = sbase;
    uint32_t a_smem = sbase + B_BYTES;

    int bid = blockIdx.x;               // 1024 = 256 m-tiles x 4 n-tiles
    int m0 = (bid >> 2) * 128;          // flat row (b*L + t)
    int n0 = (bid & 3) * 128;           // reordered column base
    int b = m0 >> 13;
    int t0 = m0 & 8191;

    int tid = threadIdx.x;
    int warp = tid >> 5, lane = tid & 31;
    int m0w = (warp >> 2) * 32, n0w = (warp & 3) * 32;   // 4 x 4 warp grid, 32x32 tiles
    int g = lane >> 2, tg = lane & 3;

    // ---- prologue: B whole-K preload + A chunk 0 via cp.async ----
    {
        int r = tid >> 2, seg = tid & 3;
        const uint4* src = (const uint4*)(g_whp + (size_t)(n0 + r) * 128 + seg * 32);
        uint32_t dst = b_smem + (uint32_t)(r * 132 + seg * 32) * 4;
        #pragma unroll
        for (int u = 0; u < 8; u++) cpasync16(dst + u * 16, src + u);
    }
    // A^T rows: d = k (0..255), 128 halfs (256B) per row starting at t0
    const __half* Agt = g_yth + ((size_t)b * DD) * LL + t0;   // + d*LL + tloc
    {
        int r = tid >> 3, s = tid & 7;     // 64 rows, 2x16B segs per thread
        const char* src = (const char*)(Agt + (size_t)r * LL) + s * 16;
        uint32_t dst = a_smem + (uint32_t)(r * APITCH + s * 16);
        cpasync16(dst, src);
        cpasync16(dst + 128, src + 128);
    }
    asm volatile("cp.async.commit_group;" ::: "memory");
    asm volatile("cp.async.wait_group 0;" ::: "memory");
    __syncthreads();

    // per-thread base offsets
    // A (trans): krow = (lane&7) + 8*((lane>>4)&1); mcol = m0w + mi*16 + 8*((lane>>3)&1)
    uint32_t aoff[2], boff[2];
    {
        int krow = (lane & 7) + ((lane >> 4) & 1) * 8;
        int mc = ((lane >> 3) & 1) * 8;
        #pragma unroll
        for (int mi = 0; mi < 2; mi++)
            aoff[mi] = (uint32_t)(krow * APITCH + (m0w + mi * 16 + mc) * 2);
    }
    #pragma unroll
    for (int nj = 0; nj < 2; nj++)
        boff[nj] = b_smem + (uint32_t)((n0w + nj * 16 + ((lane >> 4) << 3) + (lane & 7)) * 132
                                       + ((lane >> 3) & 1) * 4) * 4;

    float acc[2][4][4];
    #pragma unroll
    for (int i = 0; i < 2; i++)
        #pragma unroll
        for (int j = 0; j < 4; j++)
            #pragma unroll
            for (int p = 0; p < 4; p++) acc[i][j][p] = 0.f;

    for (int kc = 0; kc < 4; kc++) {
        if (kc < 3) {
            int r = tid >> 3, s = tid & 7;
            const char* src = (const char*)(Agt + (size_t)((kc + 1) * 64 + r) * LL) + s * 16;
            uint32_t dst = a_smem + (uint32_t)(((kc + 1) & 1) * ACHUNK)
                         + (uint32_t)(r * APITCH + s * 16);
            cpasync16(dst, src);
            cpasync16(dst + 128, src + 128);
            asm volatile("cp.async.commit_group;" ::: "memory");
        }
        uint32_t abase = a_smem + (uint32_t)(kc & 1) * ACHUNK;
        #pragma unroll
        for (int ks = 0; ks < 4; ks++) {
            uint32_t ah[2][4], bf[2][4];
            ldsm4t(ah[0], abase + (uint32_t)(ks * 16 * APITCH) + aoff[0]);
            ldsm4t(ah[1], abase + (uint32_t)(ks * 16 * APITCH) + aoff[1]);
            ldsm4(bf[0], boff[0] + (uint32_t)(kc * 32 + ks * 8) * 4);
            ldsm4(bf[1], boff[1] + (uint32_t)(kc * 32 + ks * 8) * 4);
            // 8 mma, all distinct accumulators
            #pragma unroll
            for (int mi = 0; mi < 2; mi++)
                #pragma unroll
                for (int nj = 0; nj < 2; nj++) {
                    mma16816(acc[mi][nj * 2 + 0], ah[mi], &bf[nj][0]);
                    mma16816(acc[mi][nj * 2 + 1], ah[mi], &bf[nj][2]);
                }
        }
        if (kc < 3) {
            asm volatile("cp.async.wait_group 0;" ::: "memory");
            __syncthreads();
        }
    }

    // ---- epilogue: bias + GLU (paired cols) + residual, direct stores ----
    #pragma unroll
    for (int mi = 0; mi < 2; mi++) {
        int r0 = m0 + m0w + mi * 16 + g;
        #pragma unroll
        for (int ni = 0; ni < 4; ni++) {
            int np = n0 + n0w + ni * 8 + tg * 2;
            float bb0 = g_br[np], bb1 = g_br[np + 1];
            int oc = np >> 1;
            float s0 = acc[mi][ni][0] + bb0;
            float s1 = acc[mi][ni][1] + bb1;
            float s2 = acc[mi][ni][2] + bb0;
            float s3 = acc[mi][ni][3] + bb1;
            size_t o0 = (size_t)r0 * DD + oc;
            size_t o1 = (size_t)(r0 + 8) * DD + oc;
            out[o0] = s0 * (1.f / (1.f + __expf(-s1))) + xin[o0];
            out[o1] = s2 * (1.f / (1.f + __expf(-s3))) + xin[o1];
        }
    }
}

// ---------------- launch ---------------------------------------------------------
extern "C" void kernel_launch(void* const* d_in, const int* in_sizes, int n_in,
                              void* d_out, int out_size) {
    const float* x  = (const float*)d_in[0];  // (B, L, D)
    const float* rs = (const float*)d_in[1];  // (D,)
    const float* h0 = (const float*)d_in[2];  // (D, 2)
    const float* h1 = (const float*)d_in[3];  // (D, 2)
    const float* wv = (const float*)d_in[4];  // (15, D)
    const float* cw = (const float*)d_in[5];  // (D, 2D)
    const float* cb = (const float*)d_in[6];  // (2D,)
    float* out = (float*)d_out;

    cudaFuncSetAttribute(cascade_kernel, cudaFuncAttributeMaxDynamicSharedMemorySize, 2 * LL * 4);
    cudaFuncSetAttribute(gemm_glu_mma_kernel, cudaFuncAttributeMaxDynamicSharedMemorySize, GEMM_SMEM);

    prep_kernel<<<256, 256>>>(cw, cb);
    rmsnorm_kernel<<<BB * (LL / 32), 256>>>(x, rs);
    cascade_kernel<<<BB * DD, 256, 2 * LL * 4>>>(h0, h1, wv);
    gemm_glu_mma_kernel<<<BB * (LL / 128) * 4, 512, GEMM_SMEM>>>(x, out);
}

// round 13
// speedup vs baseline: 1.4067x; 1.4067x over previous
#include <cuda_runtime.h>
#include <cuda_bf16.h>
#include <cuda_fp16.h>
#include <cstdint>
#include <math.h>

#define BB 4
#define LL 8192
#define DD 256
#define NLEV 13
#define NOUT 512

// ---------------- scratch (static device globals; no allocation) ----------------
__device__ float g_xt[BB * DD * LL];          // rmsnorm'd x, (b,d,t) layout
__device__ __half g_yth[BB * DD * LL];        // gelu output fp16, (b,d,t) layout
__device__ __half g_yh[(size_t)BB * LL * DD]; // gelu output fp16, row-major (b*L+t, d)
__device__ uint32_t g_whp[NOUT * (DD / 2)];   // W^T reordered into GLU pairs, fp16 k-pair packed
__device__ float g_br[NOUT];                  // reordered bias

// ---------------- kernel 0: weight prep (fp16 + transpose + pair-reorder) -------
__global__ void prep_kernel(const float* __restrict__ cw, const float* __restrict__ cb) {
    int idx = blockIdx.x * 256 + threadIdx.x;
    int n = idx >> 7;
    int kp = idx & 127;
    int k0 = kp * 2;
    int oc = (n & 1) ? (DD + (n >> 1)) : (n >> 1);
    float v0 = cw[k0 * NOUT + oc];
    float v1 = cw[(k0 + 1) * NOUT + oc];
    __half2 h = __floats2half2_rn(v0, v1);
    g_whp[n * 128 + kp] = *(uint32_t*)&h;
    if (idx < NOUT) {
        int occ = (idx & 1) ? (DD + (idx >> 1)) : (idx >> 1);
        g_br[idx] = cb[occ];
    }
}

// ---------------- kernel 1: rmsnorm + transpose to (b,d,t) ----------------------
__global__ void rmsnorm_kernel(const float* __restrict__ x, const float* __restrict__ rs) {
    __shared__ float tile[32][257];
    int b = blockIdx.x >> 8;
    int t0 = (blockIdx.x & 255) * 32;
    int w = threadIdx.x >> 5, lane = threadIdx.x & 31;
    #pragma unroll
    for (int rr = 0; rr < 4; rr++) {
        int tr = w * 4 + rr;
        size_t base = ((size_t)(b * LL + t0 + tr)) * DD;
        float v[8]; float ss = 0.f;
        #pragma unroll
        for (int k = 0; k < 8; k++) { v[k] = x[base + lane + 32 * k]; ss += v[k] * v[k]; }
        #pragma unroll
        for (int o = 16; o > 0; o >>= 1) ss += __shfl_xor_sync(0xffffffffu, ss, o);
        float inv = rsqrtf(ss * (1.f / DD) + 1e-6f);
        #pragma unroll
        for (int k = 0; k < 8; k++) tile[tr][lane + 32 * k] = v[k] * inv * rs[lane + 32 * k];
    }
    __syncthreads();
    #pragma unroll 8
    for (int dd = 0; dd < 32; dd++) {
        int d = w * 32 + dd;
        g_xt[((size_t)(b * DD + d)) * LL + t0 + lane] = tile[lane][d];
    }
}

// ---------------- kernel 2: 13-level dilated depthwise cascade + gelu -----------
// 512 threads x 16 elements: fewer regs/thread -> 1024 threads/SM at 64KB smem.
// Levels 0-8 (dil 1..256) via smem ping-pong; levels 9-12 (dil 512..4096 = 512*c)
// are register-local (t = tid + 512*k -> prev = a[k-c]).
__device__ __forceinline__ float gelu_f(float v) {
    float u = 0.7978845608028654f * (v + 0.044715f * v * v * v);
    return 0.5f * v * (1.f + tanhf(u));
}

__global__ void __launch_bounds__(512)
cascade_kernel(const float* __restrict__ h0,
               const float* __restrict__ h1,
               const float* __restrict__ wv) {
    extern __shared__ float sb[];
    float* srcb = sb;
    float* dstb = sb + LL;
    int b = blockIdx.x >> 8, d = blockIdx.x & 255;
    float h00 = h0[d * 2], h01 = h0[d * 2 + 1];
    float h10 = h1[d * 2], h11 = h1[d * 2 + 1];
    float w0 = wv[d];
    float wlast = wv[(NLEV + 1) * DD + d];
    size_t base = ((size_t)(b * DD + d)) * LL;
    int tid = threadIdx.x;
    float a[16], y[16];
    #pragma unroll
    for (int k = 0; k < 16; k++) {
        int t = tid + 512 * k;
        a[k] = g_xt[base + t];
        srcb[t] = a[k];
        y[k] = w0 * a[k];
    }
    for (int j = 0; j < 9; j++) {
        int dil = 1 << j;
        float wj = wv[(j + 1) * DD + d];
        __syncthreads();
        #pragma unroll
        for (int k = 0; k < 16; k++) {
            int t = tid + 512 * k;
            float prev = (t >= dil) ? srcb[t - dil] : 0.f;
            y[k] += wj * (h10 * prev + h11 * a[k]);
            a[k] = h00 * prev + h01 * a[k];
            if (j != 8) dstb[t] = a[k];
        }
        float* tmp = srcb; srcb = dstb; dstb = tmp;
    }
    #pragma unroll
    for (int j = 9; j < NLEV; j++) {
        int c = 1 << (j - 9);
        float wj = wv[(j + 1) * DD + d];
        #pragma unroll
        for (int k = 15; k >= 0; k--) {
            float prev = (k >= c) ? a[k - c] : 0.f;
            y[k] += wj * (h10 * prev + h11 * a[k]);
            a[k] = h00 * prev + h01 * a[k];
        }
    }
    #pragma unroll
    for (int k = 0; k < 16; k++) {
        int t = tid + 512 * k;
        g_yth[base + t] = __float2half_rn(gelu_f(y[k] + wlast * a[k]));
    }
}

// ---------------- kernel 2b: fp16 transpose (b,d,t) -> (b*L+t, d) ---------------
__global__ void __launch_bounds__(256)
transpose_h_kernel() {
    __shared__ uint32_t s2[32][65];   // [d-pair][t] half2(even d, odd d)
    int bid = blockIdx.x;             // 4 * 128 * 4 = 2048
    int b = bid >> 9;
    int rem = bid & 511;
    int t0 = (rem >> 2) * 64;
    int d0 = (rem & 3) * 64;
    int tid = threadIdx.x;
    {
        int dp = tid >> 3, ts = tid & 7;
        const __half* p0 = g_yth + ((size_t)(b * DD + d0 + 2 * dp)) * LL + t0 + ts * 8;
        uint4 e = *(const uint4*)p0;
        uint4 o = *(const uint4*)(p0 + LL);
        __half* eh = (__half*)&e; __half* oh = (__half*)&o;
        #pragma unroll
        for (int i = 0; i < 8; i++) {
            __half2 h = __halves2half2(eh[i], oh[i]);
            s2[dp][ts * 8 + i] = *(uint32_t*)&h;
        }
    }
    __syncthreads();
    {
        int t = tid >> 2, ds = tid & 3;
        uint32_t w[8];
        #pragma unroll
        for (int i = 0; i < 8; i++) w[i] = s2[ds * 8 + i][t];
        uint4* dst = (uint4*)(g_yh + ((size_t)(b * LL + t0 + t)) * DD + d0 + ds * 16);
        dst[0] = make_uint4(w[0], w[1], w[2], w[3]);
        dst[1] = make_uint4(w[4], w[5], w[6], w[7]);
    }
}

// ---------------- kernel 3: cp.async ldmatrix GEMM + GLU + residual (R9) --------
__device__ __forceinline__ void mma16816(float* c, const uint32_t* a, const uint32_t* b) {
    asm("mma.sync.aligned.m16n8k16.row.col.f32.f16.f16.f32 "
        "{%0,%1,%2,%3}, {%4,%5,%6,%7}, {%8,%9}, {%0,%1,%2,%3};\n"
        : "+f"(c[0]), "+f"(c[1]), "+f"(c[2]), "+f"(c[3])
        : "r"(a[0]), "r"(a[1]), "r"(a[2]), "r"(a[3]), "r"(b[0]), "r"(b[1]));
}
__device__ __forceinline__ void ldsm4(uint32_t* r, uint32_t addr) {
    asm volatile("ldmatrix.sync.aligned.m8n8.x4.shared.b16 {%0,%1,%2,%3}, [%4];"
                 : "=r"(r[0]), "=r"(r[1]), "=r"(r[2]), "=r"(r[3]) : "r"(addr));
}
__device__ __forceinline__ uint32_t smem_u32(const void* p) {
    uint32_t a;
    asm("{ .reg .u64 t; cvta.to.shared.u64 t, %1; cvt.u32.u64 %0, t; }" : "=r"(a) : "l"(p));
    return a;
}
__device__ __forceinline__ void cpasync16(uint32_t dst, const void* src) {
    asm volatile("cp.async.cg.shared.global [%0], [%1], 16;" :: "r"(dst), "l"(src));
}

// smem layout (bytes):
//   B:      [n=128][pitch 132 words]         = 67584
//   A bufs: 2 x [m=128][k=64 fp16, pitch 144B] = 2*18432 = 36864
#define B_BYTES   67584
#define ACHUNK    18432
#define GEMM_SMEM (B_BYTES + 2 * ACHUNK)

__global__ void __launch_bounds__(512, 2)
gemm_glu_mma_kernel(const float* __restrict__ xin, float* __restrict__ out) {
    extern __shared__ char smem[];
    uint32_t sbase = smem_u32(smem);
    uint32_t b_smem = sbase;
    uint32_t a_smem = sbase + B_BYTES;

    int bid = blockIdx.x;               // 1024 = 256 m-tiles x 4 n-tiles
    int m0 = (bid >> 2) * 128;          // flat row (b*L + t)
    int n0 = (bid & 3) * 128;           // reordered column base

    int tid = threadIdx.x;
    int warp = tid >> 5, lane = tid & 31;
    int m0w = (warp >> 2) * 32, n0w = (warp & 3) * 32;
    int g = lane >> 2, tg = lane & 3;

    // ---- prologue: B whole-K preload + A chunk 0 via cp.async ----
    {
        int r = tid >> 2, seg = tid & 3;
        const uint4* src = (const uint4*)(g_whp + (size_t)(n0 + r) * 128 + seg * 32);
        uint32_t dst = b_smem + (uint32_t)(r * 132 + seg * 32) * 4;
        #pragma unroll
        for (int u = 0; u < 8; u++) cpasync16(dst + u * 16, src + u);
    }
    const __half* Agh = g_yh + (size_t)m0 * DD;
    {
        int r = tid >> 2, s = tid & 3;
        const char* src = (const char*)(Agh + (size_t)r * DD) + s * 16;
        uint32_t dst = a_smem + (uint32_t)(r * 144 + s * 16);
        cpasync16(dst, src);
        cpasync16(dst + 64, src + 64);
    }
    asm volatile("cp.async.commit_group;" ::: "memory");
    asm volatile("cp.async.wait_group 0;" ::: "memory");
    __syncthreads();

    // ldmatrix per-thread base offsets
    uint32_t aoff[2], boff[2];
    #pragma unroll
    for (int mi = 0; mi < 2; mi++)
        aoff[mi] = (uint32_t)((m0w + mi * 16 + (lane & 15)) * 144 + (lane >> 4) * 16);
    #pragma unroll
    for (int nj = 0; nj < 2; nj++)
        boff[nj] = b_smem + (uint32_t)((n0w + nj * 16 + ((lane >> 4) << 3) + (lane & 7)) * 132
                                       + ((lane >> 3) & 1) * 4) * 4;

    float acc[2][4][4];
    #pragma unroll
    for (int i = 0; i < 2; i++)
        #pragma unroll
        for (int j = 0; j < 4; j++)
            #pragma unroll
            for (int p = 0; p < 4; p++) acc[i][j][p] = 0.f;

    for (int kc = 0; kc < 4; kc++) {
        if (kc < 3) {
            int r = tid >> 2, s = tid & 3;
            const char* src = (const char*)(Agh + (size_t)r * DD + (kc + 1) * 64) + s * 16;
            uint32_t dst = a_smem + (uint32_t)(((kc + 1) & 1) * ACHUNK) + (uint32_t)(r * 144 + s * 16);
            cpasync16(dst, src);
            cpasync16(dst + 64, src + 64);
            asm volatile("cp.async.commit_group;" ::: "memory");
        }
        uint32_t abase = a_smem + (uint32_t)(kc & 1) * ACHUNK;
        #pragma unroll
        for (int ks = 0; ks < 4; ks++) {
            uint32_t ah[2][4], bf[2][4];
            ldsm4(ah[0], abase + aoff[0] + ks * 32);
            ldsm4(ah[1], abase + aoff[1] + ks * 32);
            ldsm4(bf[0], boff[0] + (uint32_t)(kc * 32 + ks * 8) * 4);
            ldsm4(bf[1], boff[1] + (uint32_t)(kc * 32 + ks * 8) * 4);
            // 8 mma, all distinct accumulators
            #pragma unroll
            for (int mi = 0; mi < 2; mi++)
                #pragma unroll
                for (int nj = 0; nj < 2; nj++) {
                    mma16816(acc[mi][nj * 2 + 0], ah[mi], &bf[nj][0]);
                    mma16816(acc[mi][nj * 2 + 1], ah[mi], &bf[nj][2]);
                }
        }
        if (kc < 3) {
            asm volatile("cp.async.wait_group 0;" ::: "memory");
            __syncthreads();
        }
    }

    // ---- epilogue: bias + GLU (paired cols) + residual, direct stores ----
    #pragma unroll
    for (int mi = 0; mi < 2; mi++) {
        int r0 = m0 + m0w + mi * 16 + g;
        #pragma unroll
        for (int ni = 0; ni < 4; ni++) {
            int np = n0 + n0w + ni * 8 + tg * 2;
            float bb0 = g_br[np], bb1 = g_br[np + 1];
            int oc = np >> 1;
            float s0 = acc[mi][ni][0] + bb0;
            float s1 = acc[mi][ni][1] + bb1;
            float s2 = acc[mi][ni][2] + bb0;
            float s3 = acc[mi][ni][3] + bb1;
            size_t o0 = (size_t)r0 * DD + oc;
            size_t o1 = (size_t)(r0 + 8) * DD + oc;
            out[o0] = s0 * (1.f / (1.f + __expf(-s1))) + xin[o0];
            out[o1] = s2 * (1.f / (1.f + __expf(-s3))) + xin[o1];
        }
    }
}

// ---------------- launch ---------------------------------------------------------
extern "C" void kernel_launch(void* const* d_in, const int* in_sizes, int n_in,
                              void* d_out, int out_size) {
    const float* x  = (const float*)d_in[0];  // (B, L, D)
    const float* rs = (const float*)d_in[1];  // (D,)
    const float* h0 = (const float*)d_in[2];  // (D, 2)
    const float* h1 = (const float*)d_in[3];  // (D, 2)
    const float* wv = (const float*)d_in[4];  // (15, D)
    const float* cw = (const float*)d_in[5];  // (D, 2D)
    const float* cb = (const float*)d_in[6];  // (2D,)
    float* out = (float*)d_out;

    cudaFuncSetAttribute(cascade_kernel, cudaFuncAttributeMaxDynamicSharedMemorySize, 2 * LL * 4);
    cudaFuncSetAttribute(gemm_glu_mma_kernel, cudaFuncAttributeMaxDynamicSharedMemorySize, GEMM_SMEM);

    prep_kernel<<<256, 256>>>(cw, cb);
    rmsnorm_kernel<<<BB * (LL / 32), 256>>>(x, rs);
    cascade_kernel<<<BB * DD, 512, 2 * LL * 4>>>(h0, h1, wv);
    transpose_h_kernel<<<BB * (LL / 64) * (DD / 64), 256>>>();
    gemm_glu_mma_kernel<<<BB * (LL / 128) * 4, 512, GEMM_SMEM>>>(x, out);
}

// round 14
// speedup vs baseline: 1.4952x; 1.0629x over previous
#include <cuda_runtime.h>
#include <cuda_bf16.h>
#include <cuda_fp16.h>
#include <cstdint>
#include <math.h>

#define BB 4
#define LL 8192
#define DD 256
#define NLEV 13
#define NOUT 512

// ---------------- scratch (static device globals; no allocation) ----------------
__device__ float g_xt[BB * DD * LL];          // rmsnorm'd x, (b,d,t) layout
__device__ __half g_yth[BB * DD * LL];        // gelu output fp16, (b,d,t) layout
__device__ __half g_yh[(size_t)BB * LL * DD]; // gelu output fp16, row-major (b*L+t, d)
__device__ uint32_t g_whp[NOUT * (DD / 2)];   // W^T reordered into GLU pairs, fp16 k-pair packed
__device__ float g_br[NOUT];                  // reordered bias

// ---------------- kernel 0: weight prep (fp16 + transpose + pair-reorder) -------
__global__ void prep_kernel(const float* __restrict__ cw, const float* __restrict__ cb) {
    int idx = blockIdx.x * 256 + threadIdx.x;
    int n = idx >> 7;
    int kp = idx & 127;
    int k0 = kp * 2;
    int oc = (n & 1) ? (DD + (n >> 1)) : (n >> 1);
    float v0 = cw[k0 * NOUT + oc];
    float v1 = cw[(k0 + 1) * NOUT + oc];
    __half2 h = __floats2half2_rn(v0, v1);
    g_whp[n * 128 + kp] = *(uint32_t*)&h;
    if (idx < NOUT) {
        int occ = (idx & 1) ? (DD + (idx >> 1)) : (idx >> 1);
        g_br[idx] = cb[occ];
    }
}

// ---------------- kernel 1: rmsnorm + transpose to (b,d,t) ----------------------
__global__ void rmsnorm_kernel(const float* __restrict__ x, const float* __restrict__ rs) {
    __shared__ float tile[32][257];
    int b = blockIdx.x >> 8;
    int t0 = (blockIdx.x & 255) * 32;
    int w = threadIdx.x >> 5, lane = threadIdx.x & 31;
    #pragma unroll
    for (int rr = 0; rr < 4; rr++) {
        int tr = w * 4 + rr;
        size_t base = ((size_t)(b * LL + t0 + tr)) * DD;
        float v[8]; float ss = 0.f;
        #pragma unroll
        for (int k = 0; k < 8; k++) { v[k] = x[base + lane + 32 * k]; ss += v[k] * v[k]; }
        #pragma unroll
        for (int o = 16; o > 0; o >>= 1) ss += __shfl_xor_sync(0xffffffffu, ss, o);
        float inv = rsqrtf(ss * (1.f / DD) + 1e-6f);
        #pragma unroll
        for (int k = 0; k < 8; k++) tile[tr][lane + 32 * k] = v[k] * inv * rs[lane + 32 * k];
    }
    __syncthreads();
    #pragma unroll 8
    for (int dd = 0; dd < 32; dd++) {
        int d = w * 32 + dd;
        g_xt[((size_t)(b * DD + d)) * LL + t0 + lane] = tile[lane][d];
    }
}

// ---------------- kernel 2: 13-level dilated depthwise cascade + gelu -----------
// float2-pair decomposition: thread owns elements (2p, 2p+1), p = tid + 512k.
// Levels 0-9 (dil 1..512) via smem ping-pong, one float2 LDS+STS per pair/level
// (dil=1 uses one scalar LDS for the left boundary). Levels 10-12 (dil 1024..4096,
// pair-offset 512c) are register-local.
__device__ __forceinline__ float gelu_f(float v) {
    float u = 0.7978845608028654f * (v + 0.044715f * v * v * v);
    return 0.5f * v * (1.f + tanhf(u));
}

__global__ void __launch_bounds__(512)
cascade_kernel(const float* __restrict__ h0,
               const float* __restrict__ h1,
               const float* __restrict__ wv) {
    extern __shared__ float sb[];
    float2* sB = (float2*)sb;            // 4096 pairs
    float2* dB = (float2*)sb + 4096;
    int b = blockIdx.x >> 8, d = blockIdx.x & 255;
    float h00 = h0[d * 2], h01 = h0[d * 2 + 1];
    float h10 = h1[d * 2], h11 = h1[d * 2 + 1];
    float w0 = wv[d];
    float wlast = wv[(NLEV + 1) * DD + d];
    size_t base = ((size_t)(b * DD + d)) * LL;
    int tid = threadIdx.x;
    float2 a[8], y[8];

    const float2* px = (const float2*)(g_xt + base);
    #pragma unroll
    for (int k = 0; k < 8; k++) {
        int p = tid + 512 * k;
        float2 v = px[p];
        a[k] = v;
        sB[p] = v;
        y[k].x = w0 * v.x;
        y[k].y = w0 * v.y;
    }

    // ---- level 0: dil = 1 (scalar boundary read) ----
    {
        float wj = wv[DD + d];
        __syncthreads();
        #pragma unroll
        for (int k = 0; k < 8; k++) {
            int p = tid + 512 * k;
            float prev0 = (p > 0) ? sb[2 * p - 1] : 0.f;
            float prev1 = a[k].x;
            y[k].x += wj * (h10 * prev0 + h11 * a[k].x);
            y[k].y += wj * (h10 * prev1 + h11 * a[k].y);
            a[k].x = h00 * prev0 + h01 * a[k].x;
            a[k].y = h00 * prev1 + h01 * a[k].y;
            dB[p] = a[k];
        }
        float2* tmp = sB; sB = dB; dB = tmp;
    }

    // ---- levels 1..9: dil = 2..512, pair-offset h = dil/2 ----
    for (int j = 1; j <= 9; j++) {
        int h = 1 << (j - 1);
        float wj = wv[(j + 1) * DD + d];
        __syncthreads();
        #pragma unroll
        for (int k = 0; k < 8; k++) {
            int p = tid + 512 * k;
            float2 prev = (p >= h) ? sB[p - h] : make_float2(0.f, 0.f);
            y[k].x += wj * (h10 * prev.x + h11 * a[k].x);
            y[k].y += wj * (h10 * prev.y + h11 * a[k].y);
            a[k].x = h00 * prev.x + h01 * a[k].x;
            a[k].y = h00 * prev.y + h01 * a[k].y;
            if (j != 9) dB[p] = a[k];
        }
        float2* tmp = sB; sB = dB; dB = tmp;
    }

    // ---- levels 10..12: dil = 1024,2048,4096 -> pair-offset 512c, c = 1,2,4 ----
    #pragma unroll
    for (int j3 = 0; j3 < 3; j3++) {
        int c = 1 << j3;
        float wj = wv[(11 + j3) * DD + d];
        #pragma unroll
        for (int k = 7; k >= 0; k--) {
            float2 prev = (k >= c) ? a[k - c] : make_float2(0.f, 0.f);
            y[k].x += wj * (h10 * prev.x + h11 * a[k].x);
            y[k].y += wj * (h10 * prev.y + h11 * a[k].y);
            a[k].x = h00 * prev.x + h01 * a[k].x;
            a[k].y = h00 * prev.y + h01 * a[k].y;
        }
    }

    __half2* po = (__half2*)(g_yth + base);
    #pragma unroll
    for (int k = 0; k < 8; k++) {
        int p = tid + 512 * k;
        float r0 = gelu_f(y[k].x + wlast * a[k].x);
        float r1 = gelu_f(y[k].y + wlast * a[k].y);
        po[p] = __floats2half2_rn(r0, r1);
    }
}

// ---------------- kernel 2b: fp16 transpose (b,d,t) -> (b*L+t, d) ---------------
__global__ void __launch_bounds__(256)
transpose_h_kernel() {
    __shared__ uint32_t s2[32][65];   // [d-pair][t] half2(even d, odd d)
    int bid = blockIdx.x;             // 4 * 128 * 4 = 2048
    int b = bid >> 9;
    int rem = bid & 511;
    int t0 = (rem >> 2) * 64;
    int d0 = (rem & 3) * 64;
    int tid = threadIdx.x;
    {
        int dp = tid >> 3, ts = tid & 7;
        const __half* p0 = g_yth + ((size_t)(b * DD + d0 + 2 * dp)) * LL + t0 + ts * 8;
        uint4 e = *(const uint4*)p0;
        uint4 o = *(const uint4*)(p0 + LL);
        __half* eh = (__half*)&e; __half* oh = (__half*)&o;
        #pragma unroll
        for (int i = 0; i < 8; i++) {
            __half2 h = __halves2half2(eh[i], oh[i]);
            s2[dp][ts * 8 + i] = *(uint32_t*)&h;
        }
    }
    __syncthreads();
    {
        int t = tid >> 2, ds = tid & 3;
        uint32_t w[8];
        #pragma unroll
        for (int i = 0; i < 8; i++) w[i] = s2[ds * 8 + i][t];
        uint4* dst = (uint4*)(g_yh + ((size_t)(b * LL + t0 + t)) * DD + d0 + ds * 16);
        dst[0] = make_uint4(w[0], w[1], w[2], w[3]);
        dst[1] = make_uint4(w[4], w[5], w[6], w[7]);
    }
}

// ---------------- kernel 3: cp.async ldmatrix GEMM + GLU + residual (R9) --------
__device__ __forceinline__ void mma16816(float* c, const uint32_t* a, const uint32_t* b) {
    asm("mma.sync.aligned.m16n8k16.row.col.f32.f16.f16.f32 "
        "{%0,%1,%2,%3}, {%4,%5,%6,%7}, {%8,%9}, {%0,%1,%2,%3};\n"
        : "+f"(c[0]), "+f"(c[1]), "+f"(c[2]), "+f"(c[3])
        : "r"(a[0]), "r"(a[1]), "r"(a[2]), "r"(a[3]), "r"(b[0]), "r"(b[1]));
}
__device__ __forceinline__ void ldsm4(uint32_t* r, uint32_t addr) {
    asm volatile("ldmatrix.sync.aligned.m8n8.x4.shared.b16 {%0,%1,%2,%3}, [%4];"
                 : "=r"(r[0]), "=r"(r[1]), "=r"(r[2]), "=r"(r[3]) : "r"(addr));
}
__device__ __forceinline__ uint32_t smem_u32(const void* p) {
    uint32_t a;
    asm("{ .reg .u64 t; cvta.to.shared.u64 t, %1; cvt.u32.u64 %0, t; }" : "=r"(a) : "l"(p));
    return a;
}
__device__ __forceinline__ void cpasync16(uint32_t dst, const void* src) {
    asm volatile("cp.async.cg.shared.global [%0], [%1], 16;" :: "r"(dst), "l"(src));
}

// smem layout (bytes):
//   B:      [n=128][pitch 132 words]         = 67584
//   A bufs: 2 x [m=128][k=64 fp16, pitch 144B] = 2*18432 = 36864
#define B_BYTES   67584
#define ACHUNK    18432
#define GEMM_SMEM (B_BYTES + 2 * ACHUNK)

__global__ void __launch_bounds__(512, 2)
gemm_glu_mma_kernel(const float* __restrict__ xin, float* __restrict__ out) {
    extern __shared__ char smem[];
    uint32_t sbase = smem_u32(smem);
    uint32_t b_smem = sbase;
    uint32_t a_smem = sbase + B_BYTES;

    int bid = blockIdx.x;               // 1024 = 256 m-tiles x 4 n-tiles
    int m0 = (bid >> 2) * 128;          // flat row (b*L + t)
    int n0 = (bid & 3) * 128;           // reordered column base

    int tid = threadIdx.x;
    int warp = tid >> 5, lane = tid & 31;
    int m0w = (warp >> 2) * 32, n0w = (warp & 3) * 32;
    int g = lane >> 2, tg = lane & 3;

    // ---- prologue: B whole-K preload + A chunk 0 via cp.async ----
    {
        int r = tid >> 2, seg = tid & 3;
        const uint4* src = (const uint4*)(g_whp + (size_t)(n0 + r) * 128 + seg * 32);
        uint32_t dst = b_smem + (uint32_t)(r * 132 + seg * 32) * 4;
        #pragma unroll
        for (int u = 0; u < 8; u++) cpasync16(dst + u * 16, src + u);
    }
    const __half* Agh = g_yh + (size_t)m0 * DD;
    {
        int r = tid >> 2, s = tid & 3;
        const char* src = (const char*)(Agh + (size_t)r * DD) + s * 16;
        uint32_t dst = a_smem + (uint32_t)(r * 144 + s * 16);
        cpasync16(dst, src);
        cpasync16(dst + 64, src + 64);
    }
    asm volatile("cp.async.commit_group;" ::: "memory");
    asm volatile("cp.async.wait_group 0;" ::: "memory");
    __syncthreads();

    // ldmatrix per-thread base offsets
    uint32_t aoff[2], boff[2];
    #pragma unroll
    for (int mi = 0; mi < 2; mi++)
        aoff[mi] = (uint32_t)((m0w + mi * 16 + (lane & 15)) * 144 + (lane >> 4) * 16);
    #pragma unroll
    for (int nj = 0; nj < 2; nj++)
        boff[nj] = b_smem + (uint32_t)((n0w + nj * 16 + ((lane >> 4) << 3) + (lane & 7)) * 132
                                       + ((lane >> 3) & 1) * 4) * 4;

    float acc[2][4][4];
    #pragma unroll
    for (int i = 0; i < 2; i++)
        #pragma unroll
        for (int j = 0; j < 4; j++)
            #pragma unroll
            for (int p = 0; p < 4; p++) acc[i][j][p] = 0.f;

    for (int kc = 0; kc < 4; kc++) {
        if (kc < 3) {
            int r = tid >> 2, s = tid & 3;
            const char* src = (const char*)(Agh + (size_t)r * DD + (kc + 1) * 64) + s * 16;
            uint32_t dst = a_smem + (uint32_t)(((kc + 1) & 1) * ACHUNK) + (uint32_t)(r * 144 + s * 16);
            cpasync16(dst, src);
            cpasync16(dst + 64, src + 64);
            asm volatile("cp.async.commit_group;" ::: "memory");
        }
        uint32_t abase = a_smem + (uint32_t)(kc & 1) * ACHUNK;
        #pragma unroll
        for (int ks = 0; ks < 4; ks++) {
            uint32_t ah[2][4], bf[2][4];
            ldsm4(ah[0], abase + aoff[0] + ks * 32);
            ldsm4(ah[1], abase + aoff[1] + ks * 32);
            ldsm4(bf[0], boff[0] + (uint32_t)(kc * 32 + ks * 8) * 4);
            ldsm4(bf[1], boff[1] + (uint32_t)(kc * 32 + ks * 8) * 4);
            // 8 mma, all distinct accumulators
            #pragma unroll
            for (int mi = 0; mi < 2; mi++)
                #pragma unroll
                for (int nj = 0; nj < 2; nj++) {
                    mma16816(acc[mi][nj * 2 + 0], ah[mi], &bf[nj][0]);
                    mma16816(acc[mi][nj * 2 + 1], ah[mi], &bf[nj][2]);
                }
        }
        if (kc < 3) {
            asm volatile("cp.async.wait_group 0;" ::: "memory");
            __syncthreads();
        }
    }

    // ---- epilogue: bias + GLU (paired cols) + residual, direct stores ----
    #pragma unroll
    for (int mi = 0; mi < 2; mi++) {
        int r0 = m0 + m0w + mi * 16 + g;
        #pragma unroll
        for (int ni = 0; ni < 4; ni++) {
            int np = n0 + n0w + ni * 8 + tg * 2;
            float bb0 = g_br[np], bb1 = g_br[np + 1];
            int oc = np >> 1;
            float s0 = acc[mi][ni][0] + bb0;
            float s1 = acc[mi][ni][1] + bb1;
            float s2 = acc[mi][ni][2] + bb0;
            float s3 = acc[mi][ni][3] + bb1;
            size_t o0 = (size_t)r0 * DD + oc;
            size_t o1 = (size_t)(r0 + 8) * DD + oc;
            out[o0] = s0 * (1.f / (1.f + __expf(-s1))) + xin[o0];
            out[o1] = s2 * (1.f / (1.f + __expf(-s3))) + xin[o1];
        }
    }
}

// ---------------- launch ---------------------------------------------------------
extern "C" void kernel_launch(void* const* d_in, const int* in_sizes, int n_in,
                              void* d_out, int out_size) {
    const float* x  = (const float*)d_in[0];  // (B, L, D)
    const float* rs = (const float*)d_in[1];  // (D,)
    const float* h0 = (const float*)d_in[2];  // (D, 2)
    const float* h1 = (const float*)d_in[3];  // (D, 2)
    const float* wv = (const float*)d_in[4];  // (15, D)
    const float* cw = (const float*)d_in[5];  // (D, 2D)
    const float* cb = (const float*)d_in[6];  // (2D,)
    float* out = (float*)d_out;

    cudaFuncSetAttribute(cascade_kernel, cudaFuncAttributeMaxDynamicSharedMemorySize, 2 * LL * 4);
    cudaFuncSetAttribute(gemm_glu_mma_kernel, cudaFuncAttributeMaxDynamicSharedMemorySize, GEMM_SMEM);

    prep_kernel<<<256, 256>>>(cw, cb);
    rmsnorm_kernel<<<BB * (LL / 32), 256>>>(x, rs);
    cascade_kernel<<<BB * DD, 512, 2 * LL * 4>>>(h0, h1, wv);
    transpose_h_kernel<<<BB * (LL / 64) * (DD / 64), 256>>>();
    gemm_glu_mma_kernel<<<BB * (LL / 128) * 4, 512, GEMM_SMEM>>>(x, out);
}

// round 15
// speedup vs baseline: 1.5236x; 1.0190x over previous
#include <cuda_runtime.h>
#include <cuda_bf16.h>
#include <cuda_fp16.h>
#include <cstdint>
#include <math.h>

#define BB 4
#define LL 8192
#define DD 256
#define NLEV 13
#define NOUT 512

// ---------------- scratch (static device globals; no allocation) ----------------
__device__ float g_xt[BB * DD * LL];          // rmsnorm'd x, (b,d,t) layout
__device__ __half g_yth[BB * DD * LL];        // gelu output fp16, (b,d,t) layout
__device__ __half g_yh[(size_t)BB * LL * DD]; // gelu output fp16, row-major (b*L+t, d)
__device__ uint32_t g_whp[NOUT * (DD / 2)];   // W^T reordered into GLU pairs, fp16 k-pair packed
__device__ float g_br[NOUT];                  // reordered bias

// ---------------- kernel 0: weight prep (fp16 + transpose + pair-reorder) -------
__global__ void prep_kernel(const float* __restrict__ cw, const float* __restrict__ cb) {
    int idx = blockIdx.x * 256 + threadIdx.x;
    int n = idx >> 7;
    int kp = idx & 127;
    int k0 = kp * 2;
    int oc = (n & 1) ? (DD + (n >> 1)) : (n >> 1);
    float v0 = cw[k0 * NOUT + oc];
    float v1 = cw[(k0 + 1) * NOUT + oc];
    __half2 h = __floats2half2_rn(v0, v1);
    g_whp[n * 128 + kp] = *(uint32_t*)&h;
    if (idx < NOUT) {
        int occ = (idx & 1) ? (DD + (idx >> 1)) : (idx >> 1);
        g_br[idx] = cb[occ];
    }
}

// ---------------- kernel 1: rmsnorm + transpose to (b,d,t) ----------------------
__global__ void rmsnorm_kernel(const float* __restrict__ x, const float* __restrict__ rs) {
    __shared__ float tile[32][257];
    int b = blockIdx.x >> 8;
    int t0 = (blockIdx.x & 255) * 32;
    int w = threadIdx.x >> 5, lane = threadIdx.x & 31;
    #pragma unroll
    for (int rr = 0; rr < 4; rr++) {
        int tr = w * 4 + rr;
        size_t base = ((size_t)(b * LL + t0 + tr)) * DD;
        float v[8]; float ss = 0.f;
        #pragma unroll
        for (int k = 0; k < 8; k++) { v[k] = x[base + lane + 32 * k]; ss += v[k] * v[k]; }
        #pragma unroll
        for (int o = 16; o > 0; o >>= 1) ss += __shfl_xor_sync(0xffffffffu, ss, o);
        float inv = rsqrtf(ss * (1.f / DD) + 1e-6f);
        #pragma unroll
        for (int k = 0; k < 8; k++) tile[tr][lane + 32 * k] = v[k] * inv * rs[lane + 32 * k];
    }
    __syncthreads();
    #pragma unroll 8
    for (int dd = 0; dd < 32; dd++) {
        int d = w * 32 + dd;
        g_xt[((size_t)(b * DD + d)) * LL + t0 + lane] = tile[lane][d];
    }
}

// ---------------- kernel 2: 13-level dilated depthwise cascade + gelu -----------
// float4-quad decomposition: thread owns elements (4p..4p+3), p = tid + 512k.
// dil=1: scalar boundary LDS; dil=2: float2 boundary LDS; dil=4..1024: one
// LDS.128 per quad; dil=2048,4096: register-local (quad offset 512c).
__device__ __forceinline__ float gelu_f(float v) {
    float u = 0.7978845608028654f * (v + 0.044715f * v * v * v);
    return 0.5f * v * (1.f + tanhf(u));
}

__global__ void __launch_bounds__(512)
cascade_kernel(const float* __restrict__ h0,
               const float* __restrict__ h1,
               const float* __restrict__ wv) {
    extern __shared__ float sb[];
    float4* sB = (float4*)sb;            // 2048 quads
    float4* dB = (float4*)sb + 2048;
    int b = blockIdx.x >> 8, d = blockIdx.x & 255;
    float h00 = h0[d * 2], h01 = h0[d * 2 + 1];
    float h10 = h1[d * 2], h11 = h1[d * 2 + 1];
    float w0 = wv[d];
    float wlast = wv[(NLEV + 1) * DD + d];
    size_t base = ((size_t)(b * DD + d)) * LL;
    int tid = threadIdx.x;
    float4 a[4], y[4];

    const float4* px = (const float4*)(g_xt + base);
    #pragma unroll
    for (int k = 0; k < 4; k++) {
        int p = tid + 512 * k;
        float4 v = px[p];
        a[k] = v;
        sB[p] = v;
        y[k].x = w0 * v.x; y[k].y = w0 * v.y;
        y[k].z = w0 * v.z; y[k].w = w0 * v.w;
    }

    // ---- level 0: dil = 1 (scalar boundary) ----
    {
        float wj = wv[DD + d];
        __syncthreads();
        float* sf = (float*)sB;
        #pragma unroll
        for (int k = 0; k < 4; k++) {
            int p = tid + 512 * k;
            float p0 = (p > 0) ? sf[4 * p - 1] : 0.f;
            float p1 = a[k].x, p2 = a[k].y, p3 = a[k].z;
            y[k].x += wj * (h10 * p0 + h11 * a[k].x);
            y[k].y += wj * (h10 * p1 + h11 * a[k].y);
            y[k].z += wj * (h10 * p2 + h11 * a[k].z);
            y[k].w += wj * (h10 * p3 + h11 * a[k].w);
            a[k].w = h00 * p3 + h01 * a[k].w;
            a[k].z = h00 * p2 + h01 * a[k].z;
            a[k].y = h00 * p1 + h01 * a[k].y;
            a[k].x = h00 * p0 + h01 * a[k].x;
            dB[p] = a[k];
        }
        float4* tmp = sB; sB = dB; dB = tmp;
    }

    // ---- level 1: dil = 2 (float2 boundary) ----
    {
        float wj = wv[2 * DD + d];
        __syncthreads();
        float2* sf2 = (float2*)sB;
        #pragma unroll
        for (int k = 0; k < 4; k++) {
            int p = tid + 512 * k;
            float2 pp = (p > 0) ? sf2[2 * p - 1] : make_float2(0.f, 0.f);
            float p2 = a[k].x, p3 = a[k].y;
            y[k].x += wj * (h10 * pp.x + h11 * a[k].x);
            y[k].y += wj * (h10 * pp.y + h11 * a[k].y);
            y[k].z += wj * (h10 * p2 + h11 * a[k].z);
            y[k].w += wj * (h10 * p3 + h11 * a[k].w);
            a[k].w = h00 * p3 + h01 * a[k].w;
            a[k].z = h00 * p2 + h01 * a[k].z;
            a[k].y = h00 * pp.y + h01 * a[k].y;
            a[k].x = h00 * pp.x + h01 * a[k].x;
            dB[p] = a[k];
        }
        float4* tmp = sB; sB = dB; dB = tmp;
    }

    // ---- levels 2..10: dil = 4..1024, quad-offset h = dil/4 ----
    for (int j = 2; j <= 10; j++) {
        int h = 1 << (j - 2);
        float wj = wv[(j + 1) * DD + d];
        __syncthreads();
        #pragma unroll
        for (int k = 0; k < 4; k++) {
            int p = tid + 512 * k;
            float4 pr = (p >= h) ? sB[p - h] : make_float4(0.f, 0.f, 0.f, 0.f);
            y[k].x += wj * (h10 * pr.x + h11 * a[k].x);
            y[k].y += wj * (h10 * pr.y + h11 * a[k].y);
            y[k].z += wj * (h10 * pr.z + h11 * a[k].z);
            y[k].w += wj * (h10 * pr.w + h11 * a[k].w);
            a[k].x = h00 * pr.x + h01 * a[k].x;
            a[k].y = h00 * pr.y + h01 * a[k].y;
            a[k].z = h00 * pr.z + h01 * a[k].z;
            a[k].w = h00 * pr.w + h01 * a[k].w;
            if (j != 10) dB[p] = a[k];
        }
        float4* tmp = sB; sB = dB; dB = tmp;
    }

    // ---- levels 11,12: dil = 2048,4096 -> quad-offset 512c, c = 1,2 ----
    #pragma unroll
    for (int j3 = 0; j3 < 2; j3++) {
        int c = 1 << j3;
        float wj = wv[(12 + j3) * DD + d];
        #pragma unroll
        for (int k = 3; k >= 0; k--) {
            float4 pr = (k >= c) ? a[k - c] : make_float4(0.f, 0.f, 0.f, 0.f);
            y[k].x += wj * (h10 * pr.x + h11 * a[k].x);
            y[k].y += wj * (h10 * pr.y + h11 * a[k].y);
            y[k].z += wj * (h10 * pr.z + h11 * a[k].z);
            y[k].w += wj * (h10 * pr.w + h11 * a[k].w);
            a[k].x = h00 * pr.x + h01 * a[k].x;
            a[k].y = h00 * pr.y + h01 * a[k].y;
            a[k].z = h00 * pr.z + h01 * a[k].z;
            a[k].w = h00 * pr.w + h01 * a[k].w;
        }
    }

    uint2* po = (uint2*)(g_yth + base);
    #pragma unroll
    for (int k = 0; k < 4; k++) {
        int p = tid + 512 * k;
        __half2 lo = __floats2half2_rn(gelu_f(y[k].x + wlast * a[k].x),
                                       gelu_f(y[k].y + wlast * a[k].y));
        __half2 hi = __floats2half2_rn(gelu_f(y[k].z + wlast * a[k].z),
                                       gelu_f(y[k].w + wlast * a[k].w));
        po[p] = make_uint2(*(uint32_t*)&lo, *(uint32_t*)&hi);
    }
}

// ---------------- kernel 2b: fp16 transpose, 2 d-subtiles per block (MLP=4) -----
__global__ void __launch_bounds__(256)
transpose_h_kernel() {
    __shared__ uint32_t s2[2][32][65];   // [sub][d-pair][t]
    int bid = blockIdx.x;                // 4 * 128 * 2 = 1024
    int b = bid >> 8;
    int rem = bid & 255;
    int t0 = (rem >> 1) * 64;
    int d0 = (rem & 1) * 128;
    int tid = threadIdx.x;
    {
        int dp = tid >> 3, ts = tid & 7;
        const __half* p0 = g_yth + ((size_t)(b * DD + d0 + 2 * dp)) * LL + t0 + ts * 8;
        const __half* p1 = p0 + (size_t)64 * LL;
        uint4 e0 = *(const uint4*)p0;
        uint4 o0 = *(const uint4*)(p0 + LL);
        uint4 e1 = *(const uint4*)p1;
        uint4 o1 = *(const uint4*)(p1 + LL);
        __half* eh0 = (__half*)&e0; __half* oh0 = (__half*)&o0;
        __half* eh1 = (__half*)&e1; __half* oh1 = (__half*)&o1;
        #pragma unroll
        for (int i = 0; i < 8; i++) {
            __half2 ha = __halves2half2(eh0[i], oh0[i]);
            __half2 hb = __halves2half2(eh1[i], oh1[i]);
            s2[0][dp][ts * 8 + i] = *(uint32_t*)&ha;
            s2[1][dp][ts * 8 + i] = *(uint32_t*)&hb;
        }
    }
    __syncthreads();
    {
        int t = tid >> 2, ds = tid & 3;
        #pragma unroll
        for (int sub = 0; sub < 2; sub++) {
            uint32_t w[8];
            #pragma unroll
            for (int i = 0; i < 8; i++) w[i] = s2[sub][ds * 8 + i][t];
            uint4* dst = (uint4*)(g_yh + ((size_t)(b * LL + t0 + t)) * DD
                                  + d0 + sub * 64 + ds * 16);
            dst[0] = make_uint4(w[0], w[1], w[2], w[3]);
            dst[1] = make_uint4(w[4], w[5], w[6], w[7]);
        }
    }
}

// ---------------- kernel 3: cp.async ldmatrix GEMM + GLU + residual (R9) --------
__device__ __forceinline__ void mma16816(float* c, const uint32_t* a, const uint32_t* b) {
    asm("mma.sync.aligned.m16n8k16.row.col.f32.f16.f16.f32 "
        "{%0,%1,%2,%3}, {%4,%5,%6,%7}, {%8,%9}, {%0,%1,%2,%3};\n"
        : "+f"(c[0]), "+f"(c[1]), "+f"(c[2]), "+f"(c[3])
        : "r"(a[0]), "r"(a[1]), "r"(a[2]), "r"(a[3]), "r"(b[0]), "r"(b[1]));
}
__device__ __forceinline__ void ldsm4(uint32_t* r, uint32_t addr) {
    asm volatile("ldmatrix.sync.aligned.m8n8.x4.shared.b16 {%0,%1,%2,%3}, [%4];"
                 : "=r"(r[0]), "=r"(r[1]), "=r"(r[2]), "=r"(r[3]) : "r"(addr));
}
__device__ __forceinline__ uint32_t smem_u32(const void* p) {
    uint32_t a;
    asm("{ .reg .u64 t; cvta.to.shared.u64 t, %1; cvt.u32.u64 %0, t; }" : "=r"(a) : "l"(p));
    return a;
}
__device__ __forceinline__ void cpasync16(uint32_t dst, const void* src) {
    asm volatile("cp.async.cg.shared.global [%0], [%1], 16;" :: "r"(dst), "l"(src));
}

// smem layout (bytes):
//   B:      [n=128][pitch 132 words]         = 67584
//   A bufs: 2 x [m=128][k=64 fp16, pitch 144B] = 2*18432 = 36864
#define B_BYTES   67584
#define ACHUNK    18432
#define GEMM_SMEM (B_BYTES + 2 * ACHUNK)

__global__ void __launch_bounds__(512, 2)
gemm_glu_mma_kernel(const float* __restrict__ xin, float* __restrict__ out) {
    extern __shared__ char smem[];
    uint32_t sbase = smem_u32(smem);
    uint32_t b_smem = sbase;
    uint32_t a_smem = sbase + B_BYTES;

    int bid = blockIdx.x;               // 1024 = 256 m-tiles x 4 n-tiles
    int m0 = (bid >> 2) * 128;          // flat row (b*L + t)
    int n0 = (bid & 3) * 128;           // reordered column base

    int tid = threadIdx.x;
    int warp = tid >> 5, lane = tid & 31;
    int m0w = (warp >> 2) * 32, n0w = (warp & 3) * 32;
    int g = lane >> 2, tg = lane & 3;

    // ---- prologue: B whole-K preload + A chunk 0 via cp.async ----
    {
        int r = tid >> 2, seg = tid & 3;
        const uint4* src = (const uint4*)(g_whp + (size_t)(n0 + r) * 128 + seg * 32);
        uint32_t dst = b_smem + (uint32_t)(r * 132 + seg * 32) * 4;
        #pragma unroll
        for (int u = 0; u < 8; u++) cpasync16(dst + u * 16, src + u);
    }
    const __half* Agh = g_yh + (size_t)m0 * DD;
    {
        int r = tid >> 2, s = tid & 3;
        const char* src = (const char*)(Agh + (size_t)r * DD) + s * 16;
        uint32_t dst = a_smem + (uint32_t)(r * 144 + s * 16);
        cpasync16(dst, src);
        cpasync16(dst + 64, src + 64);
    }
    asm volatile("cp.async.commit_group;" ::: "memory");
    asm volatile("cp.async.wait_group 0;" ::: "memory");
    __syncthreads();

    // ldmatrix per-thread base offsets
    uint32_t aoff[2], boff[2];
    #pragma unroll
    for (int mi = 0; mi < 2; mi++)
        aoff[mi] = (uint32_t)((m0w + mi * 16 + (lane & 15)) * 144 + (lane >> 4) * 16);
    #pragma unroll
    for (int nj = 0; nj < 2; nj++)
        boff[nj] = b_smem + (uint32_t)((n0w + nj * 16 + ((lane >> 4) << 3) + (lane & 7)) * 132
                                       + ((lane >> 3) & 1) * 4) * 4;

    float acc[2][4][4];
    #pragma unroll
    for (int i = 0; i < 2; i++)
        #pragma unroll
        for (int j = 0; j < 4; j++)
            #pragma unroll
            for (int p = 0; p < 4; p++) acc[i][j][p] = 0.f;

    for (int kc = 0; kc < 4; kc++) {
        if (kc < 3) {
            int r = tid >> 2, s = tid & 3;
            const char* src = (const char*)(Agh + (size_t)r * DD + (kc + 1) * 64) + s * 16;
            uint32_t dst = a_smem + (uint32_t)(((kc + 1) & 1) * ACHUNK) + (uint32_t)(r * 144 + s * 16);
            cpasync16(dst, src);
            cpasync16(dst + 64, src + 64);
            asm volatile("cp.async.commit_group;" ::: "memory");
        }
        uint32_t abase = a_smem + (uint32_t)(kc & 1) * ACHUNK;
        #pragma unroll
        for (int ks = 0; ks < 4; ks++) {
            uint32_t ah[2][4], bf[2][4];
            ldsm4(ah[0], abase + aoff[0] + ks * 32);
            ldsm4(ah[1], abase + aoff[1] + ks * 32);
            ldsm4(bf[0], boff[0] + (uint32_t)(kc * 32 + ks * 8) * 4);
            ldsm4(bf[1], boff[1] + (uint32_t)(kc * 32 + ks * 8) * 4);
            // 8 mma, all distinct accumulators
            #pragma unroll
            for (int mi = 0; mi < 2; mi++)
                #pragma unroll
                for (int nj = 0; nj < 2; nj++) {
                    mma16816(acc[mi][nj * 2 + 0], ah[mi], &bf[nj][0]);
                    mma16816(acc[mi][nj * 2 + 1], ah[mi], &bf[nj][2]);
                }
        }
        if (kc < 3) {
            asm volatile("cp.async.wait_group 0;" ::: "memory");
            __syncthreads();
        }
    }

    // ---- epilogue: bias + GLU (paired cols) + residual, direct stores ----
    #pragma unroll
    for (int mi = 0; mi < 2; mi++) {
        int r0 = m0 + m0w + mi * 16 + g;
        #pragma unroll
        for (int ni = 0; ni < 4; ni++) {
            int np = n0 + n0w + ni * 8 + tg * 2;
            float bb0 = g_br[np], bb1 = g_br[np + 1];
            int oc = np >> 1;
            float s0 = acc[mi][ni][0] + bb0;
            float s1 = acc[mi][ni][1] + bb1;
            float s2 = acc[mi][ni][2] + bb0;
            float s3 = acc[mi][ni][3] + bb1;
            size_t o0 = (size_t)r0 * DD + oc;
            size_t o1 = (size_t)(r0 + 8) * DD + oc;
            out[o0] = s0 * (1.f / (1.f + __expf(-s1))) + xin[o0];
            out[o1] = s2 * (1.f / (1.f + __expf(-s3))) + xin[o1];
        }
    }
}

// ---------------- launch ---------------------------------------------------------
extern "C" void kernel_launch(void* const* d_in, const int* in_sizes, int n_in,
                              void* d_out, int out_size) {
    const float* x  = (const float*)d_in[0];  // (B, L, D)
    const float* rs = (const float*)d_in[1];  // (D,)
    const float* h0 = (const float*)d_in[2];  // (D, 2)
    const float* h1 = (const float*)d_in[3];  // (D, 2)
    const float* wv = (const float*)d_in[4];  // (15, D)
    const float* cw = (const float*)d_in[5];  // (D, 2D)
    const float* cb = (const float*)d_in[6];  // (2D,)
    float* out = (float*)d_out;

    cudaFuncSetAttribute(cascade_kernel, cudaFuncAttributeMaxDynamicSharedMemorySize, 2 * LL * 4);
    cudaFuncSetAttribute(gemm_glu_mma_kernel, cudaFuncAttributeMaxDynamicSharedMemorySize, GEMM_SMEM);

    prep_kernel<<<256, 256>>>(cw, cb);
    rmsnorm_kernel<<<BB * (LL / 32), 256>>>(x, rs);
    cascade_kernel<<<BB * DD, 512, 2 * LL * 4>>>(h0, h1, wv);
    transpose_h_kernel<<<BB * (LL / 64) * (DD / 128), 256>>>();
    gemm_glu_mma_kernel<<<BB * (LL / 128) * 4, 512, GEMM_SMEM>>>(x, out);
}

// round 16
// speedup vs baseline: 1.5764x; 1.0347x over previous
#include <cuda_runtime.h>
#include <cuda_bf16.h>
#include <cuda_fp16.h>
#include <cstdint>
#include <math.h>

#define BB 4
#define LL 8192
#define DD 256
#define NLEV 13
#define NOUT 512

// ---------------- scratch (static device globals; no allocation) ----------------
__device__ __half g_xth[BB * DD * LL];        // rmsnorm'd x fp16, (b,d,t) layout
__device__ __half g_yth[BB * DD * LL];        // gelu output fp16, (b,d,t) layout
__device__ __half g_yh[(size_t)BB * LL * DD]; // gelu output fp16, row-major (b*L+t, d)
__device__ uint32_t g_whp[NOUT * (DD / 2)];   // W^T reordered into GLU pairs, fp16 k-pair packed
__device__ float g_br[NOUT];                  // reordered bias

// ---------------- kernel 0: weight prep (fp16 + transpose + pair-reorder) -------
__global__ void prep_kernel(const float* __restrict__ cw, const float* __restrict__ cb) {
    int idx = blockIdx.x * 256 + threadIdx.x;
    int n = idx >> 7;
    int kp = idx & 127;
    int k0 = kp * 2;
    int oc = (n & 1) ? (DD + (n >> 1)) : (n >> 1);
    float v0 = cw[k0 * NOUT + oc];
    float v1 = cw[(k0 + 1) * NOUT + oc];
    __half2 h = __floats2half2_rn(v0, v1);
    g_whp[n * 128 + kp] = *(uint32_t*)&h;
    if (idx < NOUT) {
        int occ = (idx & 1) ? (DD + (idx >> 1)) : (idx >> 1);
        g_br[idx] = cb[occ];
    }
}

// ---------------- kernel 1: rmsnorm + transpose to fp16 (b,d,t) -----------------
// 64-t x 256-d tiles; writes half2 pairs so the (d,t) fp16 store stays 128B
// coalesced. smem tile2[32][257] uint: conflict-free in both phases.
__global__ void __launch_bounds__(256)
rmsnorm_kernel(const float* __restrict__ x, const float* __restrict__ rs) {
    __shared__ uint32_t tile2[32][257];   // [t-pair][d] half2(t even, t odd)
    int b = blockIdx.x >> 7;              // 128 blocks per batch (LL/64)
    int t0 = (blockIdx.x & 127) * 64;
    int w = threadIdx.x >> 5, lane = threadIdx.x & 31;
    #pragma unroll
    for (int pi = 0; pi < 4; pi++) {
        int tra = w * 8 + 2 * pi;         // local even t row (0..62)
        size_t ba = ((size_t)(b * LL + t0 + tra)) * DD;
        float va[8], vb[8];
        float ssa = 0.f, ssb = 0.f;
        #pragma unroll
        for (int k = 0; k < 8; k++) {
            va[k] = x[ba + lane + 32 * k];        ssa += va[k] * va[k];
            vb[k] = x[ba + DD + lane + 32 * k];   ssb += vb[k] * vb[k];
        }
        #pragma unroll
        for (int o = 16; o > 0; o >>= 1) {
            ssa += __shfl_xor_sync(0xffffffffu, ssa, o);
            ssb += __shfl_xor_sync(0xffffffffu, ssb, o);
        }
        float inva = rsqrtf(ssa * (1.f / DD) + 1e-6f);
        float invb = rsqrtf(ssb * (1.f / DD) + 1e-6f);
        int tp = w * 4 + pi;
        #pragma unroll
        for (int k = 0; k < 8; k++) {
            float r = rs[lane + 32 * k];
            __half2 h = __floats2half2_rn(va[k] * inva * r, vb[k] * invb * r);
            tile2[tp][lane + 32 * k] = *(uint32_t*)&h;
        }
    }
    __syncthreads();
    uint32_t* dst = (uint32_t*)g_xth;
    #pragma unroll 8
    for (int dd = 0; dd < 32; dd++) {
        int d = w * 32 + dd;
        dst[((size_t)(b * DD + d)) * (LL / 2) + (t0 >> 1) + lane] = tile2[lane][d];
    }
}

// ---------------- kernel 2: 13-level dilated depthwise cascade + gelu -----------
// float4-quad decomposition: thread owns elements (4p..4p+3), p = tid + 512k.
// Input read as fp16 quads (uint2), converted to fp32 in registers; smem
// pipeline stays fp32 so level arithmetic is unchanged.
__device__ __forceinline__ float gelu_f(float v) {
    float u = 0.7978845608028654f * (v + 0.044715f * v * v * v);
    return 0.5f * v * (1.f + tanhf(u));
}

__global__ void __launch_bounds__(512)
cascade_kernel(const float* __restrict__ h0,
               const float* __restrict__ h1,
               const float* __restrict__ wv) {
    extern __shared__ float sb[];
    float4* sB = (float4*)sb;            // 2048 quads
    float4* dB = (float4*)sb + 2048;
    int b = blockIdx.x >> 8, d = blockIdx.x & 255;
    float h00 = h0[d * 2], h01 = h0[d * 2 + 1];
    float h10 = h1[d * 2], h11 = h1[d * 2 + 1];
    float w0 = wv[d];
    float wlast = wv[(NLEV + 1) * DD + d];
    size_t base = ((size_t)(b * DD + d)) * LL;
    int tid = threadIdx.x;
    float4 a[4], y[4];

    const uint2* px = (const uint2*)(g_xth + base);
    #pragma unroll
    for (int k = 0; k < 4; k++) {
        int p = tid + 512 * k;
        uint2 q = px[p];
        float2 lo = __half22float2(*(__half2*)&q.x);
        float2 hi = __half22float2(*(__half2*)&q.y);
        float4 v = make_float4(lo.x, lo.y, hi.x, hi.y);
        a[k] = v;
        sB[p] = v;
        y[k].x = w0 * v.x; y[k].y = w0 * v.y;
        y[k].z = w0 * v.z; y[k].w = w0 * v.w;
    }

    // ---- level 0: dil = 1 (scalar boundary) ----
    {
        float wj = wv[DD + d];
        __syncthreads();
        float* sf = (float*)sB;
        #pragma unroll
        for (int k = 0; k < 4; k++) {
            int p = tid + 512 * k;
            float p0 = (p > 0) ? sf[4 * p - 1] : 0.f;
            float p1 = a[k].x, p2 = a[k].y, p3 = a[k].z;
            y[k].x += wj * (h10 * p0 + h11 * a[k].x);
            y[k].y += wj * (h10 * p1 + h11 * a[k].y);
            y[k].z += wj * (h10 * p2 + h11 * a[k].z);
            y[k].w += wj * (h10 * p3 + h11 * a[k].w);
            a[k].w = h00 * p3 + h01 * a[k].w;
            a[k].z = h00 * p2 + h01 * a[k].z;
            a[k].y = h00 * p1 + h01 * a[k].y;
            a[k].x = h00 * p0 + h01 * a[k].x;
            dB[p] = a[k];
        }
        float4* tmp = sB; sB = dB; dB = tmp;
    }

    // ---- level 1: dil = 2 (float2 boundary) ----
    {
        float wj = wv[2 * DD + d];
        __syncthreads();
        float2* sf2 = (float2*)sB;
        #pragma unroll
        for (int k = 0; k < 4; k++) {
            int p = tid + 512 * k;
            float2 pp = (p > 0) ? sf2[2 * p - 1] : make_float2(0.f, 0.f);
            float p2 = a[k].x, p3 = a[k].y;
            y[k].x += wj * (h10 * pp.x + h11 * a[k].x);
            y[k].y += wj * (h10 * pp.y + h11 * a[k].y);
            y[k].z += wj * (h10 * p2 + h11 * a[k].z);
            y[k].w += wj * (h10 * p3 + h11 * a[k].w);
            a[k].w = h00 * p3 + h01 * a[k].w;
            a[k].z = h00 * p2 + h01 * a[k].z;
            a[k].y = h00 * pp.y + h01 * a[k].y;
            a[k].x = h00 * pp.x + h01 * a[k].x;
            dB[p] = a[k];
        }
        float4* tmp = sB; sB = dB; dB = tmp;
    }

    // ---- levels 2..10: dil = 4..1024, quad-offset h = dil/4 ----
    for (int j = 2; j <= 10; j++) {
        int h = 1 << (j - 2);
        float wj = wv[(j + 1) * DD + d];
        __syncthreads();
        #pragma unroll
        for (int k = 0; k < 4; k++) {
            int p = tid + 512 * k;
            float4 pr = (p >= h) ? sB[p - h] : make_float4(0.f, 0.f, 0.f, 0.f);
            y[k].x += wj * (h10 * pr.x + h11 * a[k].x);
            y[k].y += wj * (h10 * pr.y + h11 * a[k].y);
            y[k].z += wj * (h10 * pr.z + h11 * a[k].z);
            y[k].w += wj * (h10 * pr.w + h11 * a[k].w);
            a[k].x = h00 * pr.x + h01 * a[k].x;
            a[k].y = h00 * pr.y + h01 * a[k].y;
            a[k].z = h00 * pr.z + h01 * a[k].z;
            a[k].w = h00 * pr.w + h01 * a[k].w;
            if (j != 10) dB[p] = a[k];
        }
        float4* tmp = sB; sB = dB; dB = tmp;
    }

    // ---- levels 11,12: dil = 2048,4096 -> quad-offset 512c, c = 1,2 ----
    #pragma unroll
    for (int j3 = 0; j3 < 2; j3++) {
        int c = 1 << j3;
        float wj = wv[(12 + j3) * DD + d];
        #pragma unroll
        for (int k = 3; k >= 0; k--) {
            float4 pr = (k >= c) ? a[k - c] : make_float4(0.f, 0.f, 0.f, 0.f);
            y[k].x += wj * (h10 * pr.x + h11 * a[k].x);
            y[k].y += wj * (h10 * pr.y + h11 * a[k].y);
            y[k].z += wj * (h10 * pr.z + h11 * a[k].z);
            y[k].w += wj * (h10 * pr.w + h11 * a[k].w);
            a[k].x = h00 * pr.x + h01 * a[k].x;
            a[k].y = h00 * pr.y + h01 * a[k].y;
            a[k].z = h00 * pr.z + h01 * a[k].z;
            a[k].w = h00 * pr.w + h01 * a[k].w;
        }
    }

    uint2* po = (uint2*)(g_yth + base);
    #pragma unroll
    for (int k = 0; k < 4; k++) {
        int p = tid + 512 * k;
        __half2 lo = __floats2half2_rn(gelu_f(y[k].x + wlast * a[k].x),
                                       gelu_f(y[k].y + wlast * a[k].y));
        __half2 hi = __floats2half2_rn(gelu_f(y[k].z + wlast * a[k].z),
                                       gelu_f(y[k].w + wlast * a[k].w));
        po[p] = make_uint2(*(uint32_t*)&lo, *(uint32_t*)&hi);
    }
}

// ---------------- kernel 2b: fp16 transpose, 2 d-subtiles per block -------------
__global__ void __launch_bounds__(256)
transpose_h_kernel() {
    __shared__ uint32_t s2[2][32][65];   // [sub][d-pair][t]
    int bid = blockIdx.x;                // 4 * 128 * 2 = 1024
    int b = bid >> 8;
    int rem = bid & 255;
    int t0 = (rem >> 1) * 64;
    int d0 = (rem & 1) * 128;
    int tid = threadIdx.x;
    {
        int dp = tid >> 3, ts = tid & 7;
        const __half* p0 = g_yth + ((size_t)(b * DD + d0 + 2 * dp)) * LL + t0 + ts * 8;
        const __half* p1 = p0 + (size_t)64 * LL;
        uint4 e0 = *(const uint4*)p0;
        uint4 o0 = *(const uint4*)(p0 + LL);
        uint4 e1 = *(const uint4*)p1;
        uint4 o1 = *(const uint4*)(p1 + LL);
        __half* eh0 = (__half*)&e0; __half* oh0 = (__half*)&o0;
        __half* eh1 = (__half*)&e1; __half* oh1 = (__half*)&o1;
        #pragma unroll
        for (int i = 0; i < 8; i++) {
            __half2 ha = __halves2half2(eh0[i], oh0[i]);
            __half2 hb = __halves2half2(eh1[i], oh1[i]);
            s2[0][dp][ts * 8 + i] = *(uint32_t*)&ha;
            s2[1][dp][ts * 8 + i] = *(uint32_t*)&hb;
        }
    }
    __syncthreads();
    {
        int t = tid >> 2, ds = tid & 3;
        #pragma unroll
        for (int sub = 0; sub < 2; sub++) {
            uint32_t w[8];
            #pragma unroll
            for (int i = 0; i < 8; i++) w[i] = s2[sub][ds * 8 + i][t];
            uint4* dst = (uint4*)(g_yh + ((size_t)(b * LL + t0 + t)) * DD
                                  + d0 + sub * 64 + ds * 16);
            dst[0] = make_uint4(w[0], w[1], w[2], w[3]);
            dst[1] = make_uint4(w[4], w[5], w[6], w[7]);
        }
    }
}

// ---------------- kernel 3: cp.async ldmatrix GEMM + GLU + residual (R9) --------
__device__ __forceinline__ void mma16816(float* c, const uint32_t* a, const uint32_t* b) {
    asm("mma.sync.aligned.m16n8k16.row.col.f32.f16.f16.f32 "
        "{%0,%1,%2,%3}, {%4,%5,%6,%7}, {%8,%9}, {%0,%1,%2,%3};\n"
        : "+f"(c[0]), "+f"(c[1]), "+f"(c[2]), "+f"(c[3])
        : "r"(a[0]), "r"(a[1]), "r"(a[2]), "r"(a[3]), "r"(b[0]), "r"(b[1]));
}
__device__ __forceinline__ void ldsm4(uint32_t* r, uint32_t addr) {
    asm volatile("ldmatrix.sync.aligned.m8n8.x4.shared.b16 {%0,%1,%2,%3}, [%4];"
                 : "=r"(r[0]), "=r"(r[1]), "=r"(r[2]), "=r"(r[3]) : "r"(addr));
}
__device__ __forceinline__ uint32_t smem_u32(const void* p) {
    uint32_t a;
    asm("{ .reg .u64 t; cvta.to.shared.u64 t, %1; cvt.u32.u64 %0, t; }" : "=r"(a) : "l"(p));
    return a;
}
__device__ __forceinline__ void cpasync16(uint32_t dst, const void* src) {
    asm volatile("cp.async.cg.shared.global [%0], [%1], 16;" :: "r"(dst), "l"(src));
}

// smem layout (bytes):
//   B:      [n=128][pitch 132 words]         = 67584
//   A bufs: 2 x [m=128][k=64 fp16, pitch 144B] = 2*18432 = 36864
#define B_BYTES   67584
#define ACHUNK    18432
#define GEMM_SMEM (B_BYTES + 2 * ACHUNK)

__global__ void __launch_bounds__(512, 2)
gemm_glu_mma_kernel(const float* __restrict__ xin, float* __restrict__ out) {
    extern __shared__ char smem[];
    uint32_t sbase = smem_u32(smem);
    uint32_t b_smem = sbase;
    uint32_t a_smem = sbase + B_BYTES;

    int bid = blockIdx.x;               // 1024 = 256 m-tiles x 4 n-tiles
    int m0 = (bid >> 2) * 128;          // flat row (b*L + t)
    int n0 = (bid & 3) * 128;           // reordered column base

    int tid = threadIdx.x;
    int warp = tid >> 5, lane = tid & 31;
    int m0w = (warp >> 2) * 32, n0w = (warp & 3) * 32;
    int g = lane >> 2, tg = lane & 3;

    // ---- prologue: B whole-K preload + A chunk 0 via cp.async ----
    {
        int r = tid >> 2, seg = tid & 3;
        const uint4* src = (const uint4*)(g_whp + (size_t)(n0 + r) * 128 + seg * 32);
        uint32_t dst = b_smem + (uint32_t)(r * 132 + seg * 32) * 4;
        #pragma unroll
        for (int u = 0; u < 8; u++) cpasync16(dst + u * 16, src + u);
    }
    const __half* Agh = g_yh + (size_t)m0 * DD;
    {
        int r = tid >> 2, s = tid & 3;
        const char* src = (const char*)(Agh + (size_t)r * DD) + s * 16;
        uint32_t dst = a_smem + (uint32_t)(r * 144 + s * 16);
        cpasync16(dst, src);
        cpasync16(dst + 64, src + 64);
    }
    asm volatile("cp.async.commit_group;" ::: "memory");
    asm volatile("cp.async.wait_group 0;" ::: "memory");
    __syncthreads();

    // ldmatrix per-thread base offsets
    uint32_t aoff[2], boff[2];
    #pragma unroll
    for (int mi = 0; mi < 2; mi++)
        aoff[mi] = (uint32_t)((m0w + mi * 16 + (lane & 15)) * 144 + (lane >> 4) * 16);
    #pragma unroll
    for (int nj = 0; nj < 2; nj++)
        boff[nj] = b_smem + (uint32_t)((n0w + nj * 16 + ((lane >> 4) << 3) + (lane & 7)) * 132
                                       + ((lane >> 3) & 1) * 4) * 4;

    float acc[2][4][4];
    #pragma unroll
    for (int i = 0; i < 2; i++)
        #pragma unroll
        for (int j = 0; j < 4; j++)
            #pragma unroll
            for (int p = 0; p < 4; p++) acc[i][j][p] = 0.f;

    for (int kc = 0; kc < 4; kc++) {
        if (kc < 3) {
            int r = tid >> 2, s = tid & 3;
            const char* src = (const char*)(Agh + (size_t)r * DD + (kc + 1) * 64) + s * 16;
            uint32_t dst = a_smem + (uint32_t)(((kc + 1) & 1) * ACHUNK) + (uint32_t)(r * 144 + s * 16);
            cpasync16(dst, src);
            cpasync16(dst + 64, src + 64);
            asm volatile("cp.async.commit_group;" ::: "memory");
        }
        uint32_t abase = a_smem + (uint32_t)(kc & 1) * ACHUNK;
        #pragma unroll
        for (int ks = 0; ks < 4; ks++) {
            uint32_t ah[2][4], bf[2][4];
            ldsm4(ah[0], abase + aoff[0] + ks * 32);
            ldsm4(ah[1], abase + aoff[1] + ks * 32);
            ldsm4(bf[0], boff[0] + (uint32_t)(kc * 32 + ks * 8) * 4);
            ldsm4(bf[1], boff[1] + (uint32_t)(kc * 32 + ks * 8) * 4);
            // 8 mma, all distinct accumulators
            #pragma unroll
            for (int mi = 0; mi < 2; mi++)
                #pragma unroll
                for (int nj = 0; nj < 2; nj++) {
                    mma16816(acc[mi][nj * 2 + 0], ah[mi], &bf[nj][0]);
                    mma16816(acc[mi][nj * 2 + 1], ah[mi], &bf[nj][2]);
                }
        }
        if (kc < 3) {
            asm volatile("cp.async.wait_group 0;" ::: "memory");
            __syncthreads();
        }
    }

    // ---- epilogue: bias + GLU (paired cols) + residual, direct stores ----
    #pragma unroll
    for (int mi = 0; mi < 2; mi++) {
        int r0 = m0 + m0w + mi * 16 + g;
        #pragma unroll
        for (int ni = 0; ni < 4; ni++) {
            int np = n0 + n0w + ni * 8 + tg * 2;
            float bb0 = g_br[np], bb1 = g_br[np + 1];
            int oc = np >> 1;
            float s0 = acc[mi][ni][0] + bb0;
            float s1 = acc[mi][ni][1] + bb1;
            float s2 = acc[mi][ni][2] + bb0;
            float s3 = acc[mi][ni][3] + bb1;
            size_t o0 = (size_t)r0 * DD + oc;
            size_t o1 = (size_t)(r0 + 8) * DD + oc;
            out[o0] = s0 * (1.f / (1.f + __expf(-s1))) + xin[o0];
            out[o1] = s2 * (1.f / (1.f + __expf(-s3))) + xin[o1];
        }
    }
}

// ---------------- launch ---------------------------------------------------------
extern "C" void kernel_launch(void* const* d_in, const int* in_sizes, int n_in,
                              void* d_out, int out_size) {
    const float* x  = (const float*)d_in[0];  // (B, L, D)
    const float* rs = (const float*)d_in[1];  // (D,)
    const float* h0 = (const float*)d_in[2];  // (D, 2)
    const float* h1 = (const float*)d_in[3];  // (D, 2)
    const float* wv = (const float*)d_in[4];  // (15, D)
    const float* cw = (const float*)d_in[5];  // (D, 2D)
    const float* cb = (const float*)d_in[6];  // (2D,)
    float* out = (float*)d_out;

    cudaFuncSetAttribute(cascade_kernel, cudaFuncAttributeMaxDynamicSharedMemorySize, 2 * LL * 4);
    cudaFuncSetAttribute(gemm_glu_mma_kernel, cudaFuncAttributeMaxDynamicSharedMemorySize, GEMM_SMEM);

    prep_kernel<<<256, 256>>>(cw, cb);
    rmsnorm_kernel<<<BB * (LL / 64), 256>>>(x, rs);
    cascade_kernel<<<BB * DD, 512, 2 * LL * 4>>>(h0, h1, wv);
    transpose_h_kernel<<<BB * (LL / 64) * (DD / 128), 256>>>();
    gemm_glu_mma_kernel<<<BB * (LL / 128) * 4, 512, GEMM_SMEM>>>(x, out);
}